// round 13
// baseline (speedup 1.0000x reference)
#include <cuda_runtime.h>
#include <math.h>

#define Bq 4
#define Sq 4096
#define Hq 1024
#define NHq 16
#define Dq 64
#define Rq 2
#define SCALEq 0.125f

// scratch (no allocation allowed)
__device__ float g_cnt[Bq*Sq*2];         // [b][s] float2 (r0,r1)
__device__ float g_xsum[Bq*Rq*Hq];       // zeroed by k_hist each call
__device__ float g_t[Bq*Hq];             // written whole by k_proj
__device__ float g_vsum[Bq*Rq*Hq];       // written whole by k_proj
__device__ float g_pdiff[Bq*NHq*Hq];
__device__ float g_bdiff[Bq*NHq];

// ================= k_hist: per-b histogram of both r + zero g_xsum =================
__global__ void __launch_bounds__(512)
k_hist(const int* __restrict__ idx) {
    __shared__ int sh0[Sq];              // 16KB
    __shared__ int sh1[Sq];              // 16KB
    int b = blockIdx.x, tid = threadIdx.x;
    for (int j = tid; j < Sq; j += 512) { sh0[j] = 0; sh1[j] = 0; }
    for (int i = tid; i < Rq*Hq; i += 512) g_xsum[b*Rq*Hq + i] = 0.f;
    __syncthreads();
    const int2* ip = (const int2*)(idx + (size_t)b * Sq * Rq);
    for (int s = tid; s < Sq; s += 512) {
        int2 p = ip[s];
        atomicAdd(&sh0[p.x], 1);
        atomicAdd(&sh1[p.y], 1);
    }
    __syncthreads();
    float2* c2 = (float2*)g_cnt + b*Sq;
    for (int j = tid; j < Sq; j += 512)
        c2[j] = make_float2((float)sh0[j], (float)sh1[j]);
}

// ================= k_xsum: xsum[b,r,:] = sum_s cnt[b,s,r]*x[b,s,:] =================
#define SCHUNKS 128
#define SROWS (Sq / SCHUNKS)             // 32
__global__ void __launch_bounds__(256)
k_xsum(const float* __restrict__ x) {
    int b = blockIdx.y, tid = threadIdx.x;
    int s0 = blockIdx.x * SROWS;
    const float2* cnt2 = (const float2*)g_cnt + b*Sq;
    const float4* xb4 = (const float4*)(x + (size_t)b * Sq * Hq);
    float4 a0 = make_float4(0.f,0.f,0.f,0.f);
    float4 a1 = make_float4(0.f,0.f,0.f,0.f);
    #pragma unroll 8
    for (int s = s0; s < s0 + SROWS; s++) {
        float2 c = cnt2[s];
        float4 xv = xb4[(size_t)s * 256 + tid];
        a0.x += c.x*xv.x; a0.y += c.x*xv.y; a0.z += c.x*xv.z; a0.w += c.x*xv.w;
        a1.x += c.y*xv.x; a1.y += c.y*xv.y; a1.z += c.y*xv.z; a1.w += c.y*xv.w;
    }
    float* o0 = &g_xsum[(b*Rq + 0)*Hq + tid*4];
    float* o1 = &g_xsum[(b*Rq + 1)*Hq + tid*4];
    atomicAdd(o0+0, a0.x); atomicAdd(o0+1, a0.y); atomicAdd(o0+2, a0.z); atomicAdd(o0+3, a0.w);
    atomicAdd(o1+0, a1.x); atomicAdd(o1+1, a1.y); atomicAdd(o1+2, a1.z); atomicAdd(o1+3, a1.w);
}

// ================= k_proj (atomic-free): t = xd@Wk (blocks 0-31) ; vsum = xsum@Wv + S*bv (32-63) =================
__global__ void __launch_bounds__(256)
k_proj(const float* __restrict__ Wk, const float* __restrict__ Wv,
       const float* __restrict__ bv) {
    __shared__ float sbuf[8*Hq];         // 32KB staging
    __shared__ float sred[8*32*8];       // 8KB partials
    int bid = blockIdx.x, tid = threadIdx.x;
    int c = tid & 31, q = tid >> 5;      // q = row-chunk 0..7

    if (bid < 32) {
        for (int i = tid; i < Bq*Hq; i += 256) {
            int bb = i >> 10, hc = i & (Hq-1);
            sbuf[i] = g_xsum[(bb*Rq + 0)*Hq + hc] - g_xsum[(bb*Rq + 1)*Hq + hc];
        }
        __syncthreads();
        int col = bid * 32 + c;
        const float* Wp = Wk + (size_t)(q*128) * Hq + col;
        float a[4] = {0.f,0.f,0.f,0.f};
        #pragma unroll 8
        for (int hc = 0; hc < 128; hc++) {
            float w = Wp[(size_t)hc * Hq];
            int g = q*128 + hc;
            a[0] += sbuf[g]*w; a[1] += sbuf[Hq+g]*w; a[2] += sbuf[2*Hq+g]*w; a[3] += sbuf[3*Hq+g]*w;
        }
        #pragma unroll
        for (int bb = 0; bb < 4; bb++) sred[(q*32 + c)*4 + bb] = a[bb];
        __syncthreads();
        if (q == 0) {
            #pragma unroll
            for (int bb = 0; bb < 4; bb++) {
                float s = 0.f;
                #pragma unroll
                for (int qq = 0; qq < 8; qq++) s += sred[(qq*32 + c)*4 + bb];
                g_t[bb*Hq + col] = s;
            }
        }
    } else {
        for (int i = tid; i < 2*Bq*Hq; i += 256) sbuf[i] = g_xsum[i];
        __syncthreads();
        int col = (bid - 32) * 32 + c;
        const float* Wp = Wv + (size_t)(q*128) * Hq + col;
        float a[8] = {0.f,0.f,0.f,0.f,0.f,0.f,0.f,0.f};
        #pragma unroll 8
        for (int hc = 0; hc < 128; hc++) {
            float w = Wp[(size_t)hc * Hq];
            int g = q*128 + hc;
            #pragma unroll
            for (int br = 0; br < 8; br++) a[br] += sbuf[br*Hq + g]*w;
        }
        #pragma unroll
        for (int br = 0; br < 8; br++) sred[(q*32 + c)*8 + br] = a[br];
        __syncthreads();
        if (q == 0) {
            float bias = 4096.f * bv[col];
            #pragma unroll
            for (int br = 0; br < 8; br++) {
                float s = 0.f;
                #pragma unroll
                for (int qq = 0; qq < 8; qq++) s += sred[(qq*32 + c)*8 + br];
                g_vsum[br*Hq + col] = s + bias;
            }
        }
    }
}

// ================= k_pdiff: warp-per-Wq-row, front-batched loads =================
__global__ void __launch_bounds__(256)
k_pdiff(const float* __restrict__ Wq, const float* __restrict__ bq) {
    __shared__ float st[Bq*Hq];          // t staged, 16KB
    int tid = threadIdx.x;
    for (int i = tid; i < Bq*Hq; i += 256) st[i] = g_t[i];
    __syncthreads();

    int warp = tid >> 5, lane = tid & 31;
    int wg = blockIdx.x * 8 + warp;

    if (wg < 1024) {
        int h = wg;
        const float4* wr = (const float4*)(Wq + (size_t)h * Hq);
        float4 w[8];
        #pragma unroll
        for (int j = 0; j < 8; j++) w[j] = wr[j*32 + lane];

        float acc[Bq][8];
        #pragma unroll
        for (int b = 0; b < Bq; b++) {
            const float4* tb = (const float4*)&st[b*Hq];
            #pragma unroll
            for (int j = 0; j < 8; j++) {
                float4 tv = tb[j*32 + lane];     // head n = 2j + (lane>>4)
                acc[b][j] = w[j].x*tv.x + w[j].y*tv.y + w[j].z*tv.z + w[j].w*tv.w;
            }
        }
        #pragma unroll
        for (int b = 0; b < Bq; b++)
            #pragma unroll
            for (int j = 0; j < 8; j++) {
                float v = acc[b][j];
                v += __shfl_xor_sync(0xffffffffu, v, 8);
                v += __shfl_xor_sync(0xffffffffu, v, 4);
                v += __shfl_xor_sync(0xffffffffu, v, 2);
                v += __shfl_xor_sync(0xffffffffu, v, 1);
                acc[b][j] = v;
            }
        if ((lane & 15) == 0) {
            int half = lane >> 4;
            #pragma unroll
            for (int b = 0; b < Bq; b++)
                #pragma unroll
                for (int j = 0; j < 8; j++)
                    g_pdiff[(b*NHq + (2*j + half))*Hq + h] = SCALEq * acc[b][j];
        }
    } else if (wg < 1024 + Bq*NHq) {
        int id = wg - 1024;
        int b = id >> 4, n = id & 15;
        float s = bq[n*Dq + lane]      * st[b*Hq + n*Dq + lane]
                + bq[n*Dq + 32 + lane] * st[b*Hq + n*Dq + 32 + lane];
        #pragma unroll
        for (int o = 16; o > 0; o >>= 1) s += __shfl_xor_sync(0xffffffffu, s, o);
        if (lane == 0) g_bdiff[b*NHq + n] = SCALEq * s;
    }
}

// ================= k_main: 2 rows/warp, low regs -> 24 warps/SM; streaming stores =================
#define SMEM_MAIN ((NHq*Hq + 2*Hq + 16) * sizeof(float))
__global__ void __launch_bounds__(256, 3)
k_main(const float* __restrict__ x, float* __restrict__ out) {
    extern __shared__ float sm[];
    float* sPd = sm;                 // [16][1024]
    float* sV0 = sm + NHq*Hq;        // [1024]
    float* sV1 = sV0 + Hq;           // [1024]
    float* sBd = sV1 + Hq;           // [16]

    int b = blockIdx.y, tid = threadIdx.x;
    {
        const float4* gp4 = (const float4*)&g_pdiff[b*NHq*Hq];
        float4* sp4 = (float4*)sPd;
        for (int i = tid; i < NHq*Hq/4; i += 256) sp4[i] = gp4[i];
        const float4* v0g = (const float4*)&g_vsum[(b*Rq + 0)*Hq];
        const float4* v1g = (const float4*)&g_vsum[(b*Rq + 1)*Hq];
        float4* s04 = (float4*)sV0; float4* s14 = (float4*)sV1;
        for (int i = tid; i < Hq/4; i += 256) { s04[i] = v0g[i]; s14[i] = v1g[i]; }
        if (tid < NHq) sBd[tid] = g_bdiff[b*NHq + tid];
    }
    __syncthreads();

    int warp = tid >> 5, lane = tid & 31;
    int r0 = blockIdx.x * 16 + warp * 2;           // 8 warps * 2 rows = 16 rows/block
    const float* xb = x + (size_t)b * Sq * Hq;
    float* ob = out + (size_t)b * Sq * Hq;

    const float4* xr0 = (const float4*)(xb + (size_t)(r0 + 0) * Hq);
    const float4* xr1 = (const float4*)(xb + (size_t)(r0 + 1) * Hq);
    const float4* sPd4 = (const float4*)sPd;

    float acc[2][NHq];
    #pragma unroll
    for (int i = 0; i < 2; i++)
        #pragma unroll
        for (int n = 0; n < NHq; n++) acc[i][n] = 0.f;

    float4 xv0 = xr0[lane], xv1 = xr1[lane];

    #pragma unroll
    for (int j = 0; j < 8; j++) {               // 8 * 32 lanes * float4 = 1024 h
        int h4 = lane + 32*j;
        float4 xn0, xn1;
        if (j < 7) { xn0 = xr0[h4 + 32]; xn1 = xr1[h4 + 32]; }
        #pragma unroll
        for (int n = 0; n < NHq; n++) {
            float4 pd = sPd4[n*256 + h4];
            acc[0][n] += xv0.x*pd.x + xv0.y*pd.y + xv0.z*pd.z + xv0.w*pd.w;
            acc[1][n] += xv1.x*pd.x + xv1.y*pd.y + xv1.z*pd.z + xv1.w*pd.w;
        }
        xv0 = xn0; xv1 = xn1;
    }

    // warp-reduce all 32 partials (butterfly -> every lane has full sums)
    #pragma unroll
    for (int i = 0; i < 2; i++)
        #pragma unroll
        for (int n = 0; n < NHq; n++) {
            float v = acc[i][n];
            v += __shfl_xor_sync(0xffffffffu, v, 16);
            v += __shfl_xor_sync(0xffffffffu, v, 8);
            v += __shfl_xor_sync(0xffffffffu, v, 4);
            v += __shfl_xor_sync(0xffffffffu, v, 2);
            v += __shfl_xor_sync(0xffffffffu, v, 1);
            acc[i][n] = 1.f / (1.f + __expf(-(v + sBd[n])));   // prob for y=0
        }

    const float4* v04 = (const float4*)sV0;
    const float4* v14 = (const float4*)sV1;
    #pragma unroll
    for (int i = 0; i < 2; i++) {
        float4* o4 = (float4*)(ob + (size_t)(r0 + i) * Hq);
        #pragma unroll
        for (int j = 0; j < 8; j++) {
            int h4 = lane + 32*j;                  // float4 index; head = h4>>4
            float ppA = acc[i][2*j];               // lane < 16 half
            float ppB = acc[i][2*j + 1];           // lane >= 16 half
            float pp = (lane & 16) ? ppB : ppA;
            float4 a = v04[h4];
            float4 c = v14[h4];
            float4 o;
            o.x = c.x + pp * (a.x - c.x);
            o.y = c.y + pp * (a.y - c.y);
            o.z = c.z + pp * (a.z - c.z);
            o.w = c.w + pp * (a.w - c.w);
            __stcs(o4 + h4, o);                    // streaming store: don't evict x from L2
        }
    }
}

extern "C" void kernel_launch(void* const* d_in, const int* in_sizes, int n_in,
                              void* d_out, int out_size) {
    const float* x  = (const float*)d_in[0];
    // d_in[1] attention_mask: unused by reference
    const float* Wq = (const float*)d_in[2];
    const float* bq = (const float*)d_in[3];
    const float* Wk = (const float*)d_in[4];
    // d_in[5] bk cancels in the score difference
    const float* Wv = (const float*)d_in[6];
    const float* bv = (const float*)d_in[7];
    const int* idx  = (const int*)d_in[8];
    float* out = (float*)d_out;

    cudaFuncSetAttribute(k_main, cudaFuncAttributeMaxDynamicSharedMemorySize, (int)SMEM_MAIN);

    k_hist<<<Bq, 512>>>(idx);
    k_xsum<<<dim3(SCHUNKS, Bq), 256>>>(x);
    k_proj<<<64, 256>>>(Wk, Wv, bv);
    k_pdiff<<<136, 256>>>(Wq, bq);
    k_main<<<dim3(Sq/16, Bq), 256, SMEM_MAIN>>>(x, out);
}

// round 14
// speedup vs baseline: 1.1472x; 1.1472x over previous
#include <cuda_runtime.h>
#include <math.h>

#define Bq 4
#define Sq 4096
#define Hq 1024
#define NHq 16
#define Dq 64
#define Rq 2
#define SCALEq 0.125f

// scratch (no allocation allowed)
__device__ float g_cnt[Bq*Sq*2];         // [b][s] float2 (r0,r1)
__device__ float g_xsum[Bq*Rq*Hq];
__device__ float g_t[Bq*Hq];             // (xsum0-xsum1) @ Wk
__device__ float g_vsum[Bq*Rq*Hq];
__device__ float g_pdiff[Bq*NHq*Hq];
__device__ float g_bdiff[Bq*NHq];

// ================= k_hist: per-b histogram of both r + buffer init =================
__global__ void __launch_bounds__(512)
k_hist(const int* __restrict__ idx, const float* __restrict__ bv) {
    __shared__ int sh0[Sq];              // 16KB
    __shared__ int sh1[Sq];              // 16KB
    int b = blockIdx.x, tid = threadIdx.x;
    for (int j = tid; j < Sq; j += 512) { sh0[j] = 0; sh1[j] = 0; }
    for (int i = tid; i < Hq; i += 512) {
        g_xsum[(b*Rq + 0)*Hq + i] = 0.f;
        g_xsum[(b*Rq + 1)*Hq + i] = 0.f;
        g_t[b*Hq + i] = 0.f;
        float sv = 4096.f * bv[i];
        g_vsum[(b*Rq + 0)*Hq + i] = sv;
        g_vsum[(b*Rq + 1)*Hq + i] = sv;
    }
    __syncthreads();
    const int2* ip = (const int2*)(idx + (size_t)b * Sq * Rq);
    for (int s = tid; s < Sq; s += 512) {
        int2 p = ip[s];
        atomicAdd(&sh0[p.x], 1);
        atomicAdd(&sh1[p.y], 1);
    }
    __syncthreads();
    float2* c2 = (float2*)g_cnt + b*Sq;
    for (int j = tid; j < Sq; j += 512)
        c2[j] = make_float2((float)sh0[j], (float)sh1[j]);
}

// ================= k_xsum: front-batched 8-deep loads =================
#define SCHUNKS 128
#define SROWS (Sq / SCHUNKS)             // 32
__global__ void __launch_bounds__(256)
k_xsum(const float* __restrict__ x) {
    int b = blockIdx.y, tid = threadIdx.x;
    int s0 = blockIdx.x * SROWS;
    const float2* cnt2 = (const float2*)g_cnt + b*Sq;
    const float4* xb4 = (const float4*)(x + (size_t)b * Sq * Hq);
    float4 a0 = make_float4(0.f,0.f,0.f,0.f);
    float4 a1 = make_float4(0.f,0.f,0.f,0.f);
    #pragma unroll
    for (int g = 0; g < SROWS/8; g++) {
        int s = s0 + g*8;
        float4 xv[8];                    // 8 independent LDG.128 in flight
        #pragma unroll
        for (int k = 0; k < 8; k++) xv[k] = xb4[(size_t)(s + k) * 256 + tid];
        float2 c[8];
        #pragma unroll
        for (int k = 0; k < 8; k++) c[k] = cnt2[s + k];
        #pragma unroll
        for (int k = 0; k < 8; k++) {
            a0.x += c[k].x*xv[k].x; a0.y += c[k].x*xv[k].y;
            a0.z += c[k].x*xv[k].z; a0.w += c[k].x*xv[k].w;
            a1.x += c[k].y*xv[k].x; a1.y += c[k].y*xv[k].y;
            a1.z += c[k].y*xv[k].z; a1.w += c[k].y*xv[k].w;
        }
    }
    float* o0 = &g_xsum[(b*Rq + 0)*Hq + tid*4];
    float* o1 = &g_xsum[(b*Rq + 1)*Hq + tid*4];
    atomicAdd(o0+0, a0.x); atomicAdd(o0+1, a0.y); atomicAdd(o0+2, a0.z); atomicAdd(o0+3, a0.w);
    atomicAdd(o1+0, a1.x); atomicAdd(o1+1, a1.y); atomicAdd(o1+2, a1.z); atomicAdd(o1+3, a1.w);
}

// ================= k_proj: t = xd@Wk (y=0) ; vsum += xsum@Wv (y=1) =================
__global__ void __launch_bounds__(256)
k_proj(const float* __restrict__ Wk, const float* __restrict__ Wv) {
    __shared__ float xa[16][8];
    int tid = threadIdx.x;
    int hc = blockIdx.x * 16;
    if (blockIdx.y == 0) {
        if (tid < 64) {
            int hl = tid >> 2, b = tid & 3;
            xa[hl][b] = g_xsum[(b*Rq + 0)*Hq + hc + hl] - g_xsum[(b*Rq + 1)*Hq + hc + hl];
        }
        __syncthreads();
        float4 acc[4];
        #pragma unroll
        for (int b = 0; b < 4; b++) acc[b] = make_float4(0.f,0.f,0.f,0.f);
        const float4* W4 = (const float4*)Wk;
        #pragma unroll
        for (int hl = 0; hl < 16; hl++) {
            float4 w = W4[(size_t)(hc + hl) * 256 + tid];
            #pragma unroll
            for (int b = 0; b < 4; b++) {
                float xv = xa[hl][b];
                acc[b].x += xv*w.x; acc[b].y += xv*w.y; acc[b].z += xv*w.z; acc[b].w += xv*w.w;
            }
        }
        #pragma unroll
        for (int b = 0; b < 4; b++) {
            float* o = &g_t[b*Hq + tid*4];
            atomicAdd(o+0, acc[b].x); atomicAdd(o+1, acc[b].y);
            atomicAdd(o+2, acc[b].z); atomicAdd(o+3, acc[b].w);
        }
    } else {
        if (tid < 128) {
            int hl = tid >> 3, br = tid & 7;
            xa[hl][br] = g_xsum[br*Hq + hc + hl];
        }
        __syncthreads();
        float4 acc[8];
        #pragma unroll
        for (int br = 0; br < 8; br++) acc[br] = make_float4(0.f,0.f,0.f,0.f);
        const float4* W4 = (const float4*)Wv;
        #pragma unroll
        for (int hl = 0; hl < 16; hl++) {
            float4 w = W4[(size_t)(hc + hl) * 256 + tid];
            #pragma unroll
            for (int br = 0; br < 8; br++) {
                float xv = xa[hl][br];
                acc[br].x += xv*w.x; acc[br].y += xv*w.y; acc[br].z += xv*w.z; acc[br].w += xv*w.w;
            }
        }
        #pragma unroll
        for (int br = 0; br < 8; br++) {
            float* o = &g_vsum[br*Hq + tid*4];
            atomicAdd(o+0, acc[br].x); atomicAdd(o+1, acc[br].y);
            atomicAdd(o+2, acc[br].z); atomicAdd(o+3, acc[br].w);
        }
    }
}

// ================= k_pdiff: warp-per-Wq-row, front-batched loads =================
__global__ void __launch_bounds__(256)
k_pdiff(const float* __restrict__ Wq, const float* __restrict__ bq) {
    __shared__ float st[Bq*Hq];          // t staged, 16KB
    int tid = threadIdx.x;
    for (int i = tid; i < Bq*Hq; i += 256) st[i] = g_t[i];
    __syncthreads();

    int warp = tid >> 5, lane = tid & 31;
    int wg = blockIdx.x * 8 + warp;

    if (wg < 1024) {
        int h = wg;
        const float4* wr = (const float4*)(Wq + (size_t)h * Hq);
        float4 w[8];
        #pragma unroll
        for (int j = 0; j < 8; j++) w[j] = wr[j*32 + lane];

        float acc[Bq][8];
        #pragma unroll
        for (int b = 0; b < Bq; b++) {
            const float4* tb = (const float4*)&st[b*Hq];
            #pragma unroll
            for (int j = 0; j < 8; j++) {
                float4 tv = tb[j*32 + lane];     // head n = 2j + (lane>>4)
                acc[b][j] = w[j].x*tv.x + w[j].y*tv.y + w[j].z*tv.z + w[j].w*tv.w;
            }
        }
        #pragma unroll
        for (int b = 0; b < Bq; b++)
            #pragma unroll
            for (int j = 0; j < 8; j++) {
                float v = acc[b][j];
                v += __shfl_xor_sync(0xffffffffu, v, 8);
                v += __shfl_xor_sync(0xffffffffu, v, 4);
                v += __shfl_xor_sync(0xffffffffu, v, 2);
                v += __shfl_xor_sync(0xffffffffu, v, 1);
                acc[b][j] = v;
            }
        if ((lane & 15) == 0) {
            int half = lane >> 4;
            #pragma unroll
            for (int b = 0; b < Bq; b++)
                #pragma unroll
                for (int j = 0; j < 8; j++)
                    g_pdiff[(b*NHq + (2*j + half))*Hq + h] = SCALEq * acc[b][j];
        }
    } else if (wg < 1024 + Bq*NHq) {
        int id = wg - 1024;
        int b = id >> 4, n = id & 15;
        float s = bq[n*Dq + lane]      * st[b*Hq + n*Dq + lane]
                + bq[n*Dq + 32 + lane] * st[b*Hq + n*Dq + 32 + lane];
        #pragma unroll
        for (int o = 16; o > 0; o >>= 1) s += __shfl_xor_sync(0xffffffffu, s, o);
        if (lane == 0) g_bdiff[b*NHq + n] = SCALEq * s;
    }
}

// ================= k_main: scalar f32, 256 thr, occ 2, 4 rows/warp; streaming stores =================
#define SMEM_MAIN ((NHq*Hq + 2*Hq + 16) * sizeof(float))
__global__ void __launch_bounds__(256, 2)
k_main(const float* __restrict__ x, float* __restrict__ out) {
    extern __shared__ float sm[];
    float* sPd = sm;                 // [16][1024]
    float* sV0 = sm + NHq*Hq;        // [1024]
    float* sV1 = sV0 + Hq;           // [1024]
    float* sBd = sV1 + Hq;           // [16]

    int b = blockIdx.y, tid = threadIdx.x;
    {
        const float4* gp4 = (const float4*)&g_pdiff[b*NHq*Hq];
        float4* sp4 = (float4*)sPd;
        for (int i = tid; i < NHq*Hq/4; i += 256) sp4[i] = gp4[i];
        const float4* v0g = (const float4*)&g_vsum[(b*Rq + 0)*Hq];
        const float4* v1g = (const float4*)&g_vsum[(b*Rq + 1)*Hq];
        float4* s04 = (float4*)sV0; float4* s14 = (float4*)sV1;
        for (int i = tid; i < Hq/4; i += 256) { s04[i] = v0g[i]; s14[i] = v1g[i]; }
        if (tid < NHq) sBd[tid] = g_bdiff[b*NHq + tid];
    }
    __syncthreads();

    int warp = tid >> 5, lane = tid & 31;
    int r0 = blockIdx.x * 32 + warp * 4;           // 8 warps * 4 rows = 32 rows/block
    const float* xb = x + (size_t)b * Sq * Hq;
    float* ob = out + (size_t)b * Sq * Hq;

    const float4* xr4[4];
    #pragma unroll
    for (int i = 0; i < 4; i++)
        xr4[i] = (const float4*)(xb + (size_t)(r0 + i) * Hq);
    const float4* sPd4 = (const float4*)sPd;

    float acc[4][NHq];
    #pragma unroll
    for (int i = 0; i < 4; i++)
        #pragma unroll
        for (int n = 0; n < NHq; n++) acc[i][n] = 0.f;

    float4 xv[4];
    #pragma unroll
    for (int i = 0; i < 4; i++) xv[i] = xr4[i][lane];

    #pragma unroll
    for (int j = 0; j < 8; j++) {               // 8 * 32 lanes * float4 = 1024 h
        int h4 = lane + 32*j;
        float4 xn[4];
        if (j < 7) {
            #pragma unroll
            for (int i = 0; i < 4; i++) xn[i] = xr4[i][h4 + 32];
        }
        #pragma unroll
        for (int n = 0; n < NHq; n++) {
            float4 pd = sPd4[n*256 + h4];
            #pragma unroll
            for (int i = 0; i < 4; i++) {
                acc[i][n] += xv[i].x*pd.x + xv[i].y*pd.y + xv[i].z*pd.z + xv[i].w*pd.w;
            }
        }
        #pragma unroll
        for (int i = 0; i < 4; i++) xv[i] = xn[i];
    }

    // warp-reduce all 64 partials (butterfly -> every lane has full sums)
    #pragma unroll
    for (int i = 0; i < 4; i++)
        #pragma unroll
        for (int n = 0; n < NHq; n++) {
            float v = acc[i][n];
            v += __shfl_xor_sync(0xffffffffu, v, 16);
            v += __shfl_xor_sync(0xffffffffu, v, 8);
            v += __shfl_xor_sync(0xffffffffu, v, 4);
            v += __shfl_xor_sync(0xffffffffu, v, 2);
            v += __shfl_xor_sync(0xffffffffu, v, 1);
            acc[i][n] = 1.f / (1.f + __expf(-(v + sBd[n])));   // prob for y=0
        }

    const float4* v04 = (const float4*)sV0;
    const float4* v14 = (const float4*)sV1;
    #pragma unroll
    for (int i = 0; i < 4; i++) {
        float4* o4 = (float4*)(ob + (size_t)(r0 + i) * Hq);
        #pragma unroll
        for (int j = 0; j < 8; j++) {
            int h4 = lane + 32*j;                  // float4 index; head = h4>>4
            float ppA = acc[i][2*j];               // lane < 16 half
            float ppB = acc[i][2*j + 1];           // lane >= 16 half
            float pp = (lane & 16) ? ppB : ppA;
            float4 a = v04[h4];
            float4 c = v14[h4];
            float4 o;
            o.x = c.x + pp * (a.x - c.x);
            o.y = c.y + pp * (a.y - c.y);
            o.z = c.z + pp * (a.z - c.z);
            o.w = c.w + pp * (a.w - c.w);
            __stcs(o4 + h4, o);                    // streaming store: keep x resident in L2
        }
    }
}

extern "C" void kernel_launch(void* const* d_in, const int* in_sizes, int n_in,
                              void* d_out, int out_size) {
    const float* x  = (const float*)d_in[0];
    // d_in[1] attention_mask: unused by reference
    const float* Wq = (const float*)d_in[2];
    const float* bq = (const float*)d_in[3];
    const float* Wk = (const float*)d_in[4];
    // d_in[5] bk cancels in the score difference
    const float* Wv = (const float*)d_in[6];
    const float* bv = (const float*)d_in[7];
    const int* idx  = (const int*)d_in[8];
    float* out = (float*)d_out;

    cudaFuncSetAttribute(k_main, cudaFuncAttributeMaxDynamicSharedMemorySize, (int)SMEM_MAIN);

    k_hist<<<Bq, 512>>>(idx, bv);
    k_xsum<<<dim3(SCHUNKS, Bq), 256>>>(x);
    k_proj<<<dim3(64, 2), 256>>>(Wk, Wv);
    k_pdiff<<<136, 256>>>(Wq, bq);
    k_main<<<dim3(Sq/32, Bq), 256, SMEM_MAIN>>>(x, out);
}